// round 7
// baseline (speedup 1.0000x reference)
#include <cuda_runtime.h>
#include <cstdint>
#include <cstddef>

#define T_TOK 8192
#define D_IN  4096
#define D_OUT 4096
#define RANK  16
#define NA    8

// ---- GEMM tile config: CTA 128x128, 4 warps of 64x64, BK=32, 3 stages ----
#define BM 128
#define BN 128
#define BK 32
#define STAGES 3
#define KTILES (D_IN / BK)          // 128
#define A_STAGE_B 16384
#define B_STAGE_B 16384
#define SMEM_TOTAL (STAGES * (A_STAGE_B + B_STAGE_B))   // 98304

// ---- scratch (__device__ globals; no allocation allowed) ----
__device__ float g_xa[(size_t)T_TOK * D_IN];    // A-fragment order, tf32-rounded
__device__ float g_wb2[(size_t)D_OUT * D_IN];   // B-fragment order, tf32-rounded
__device__ float g_Hs[T_TOK * RANK];
__device__ int   g_adp[T_TOK];

// ===========================================================================
// helpers
// ===========================================================================
__device__ __forceinline__ uint32_t smem_u32(const void* p) {
    return (uint32_t)__cvta_generic_to_shared(p);
}
__device__ __forceinline__ uint32_t f2tf(float f) {
    uint32_t u;
    asm("cvt.rna.tf32.f32 %0, %1;" : "=r"(u) : "f"(f));
    return u;
}
__device__ __forceinline__ void cp16(uint32_t dst, const void* src) {
    asm volatile("cp.async.cg.shared.global [%0], [%1], 16;\n" ::"r"(dst), "l"(src));
}
#define CP_COMMIT() asm volatile("cp.async.commit_group;\n")
#define CP_WAIT1()  asm volatile("cp.async.wait_group 1;\n")

__device__ __forceinline__ uint4 lds128(uint32_t a) {
    uint4 v;
    asm volatile("ld.shared.v4.b32 {%0,%1,%2,%3}, [%4];"
                 : "=r"(v.x), "=r"(v.y), "=r"(v.z), "=r"(v.w) : "r"(a));
    return v;
}
__device__ __forceinline__ void mma_tf32(float* c, const uint4& a, uint32_t b0, uint32_t b1) {
    asm volatile(
        "mma.sync.aligned.m16n8k8.row.col.f32.tf32.tf32.f32 "
        "{%0,%1,%2,%3},{%4,%5,%6,%7},{%8,%9},{%0,%1,%2,%3};\n"
        : "+f"(c[0]), "+f"(c[1]), "+f"(c[2]), "+f"(c[3])
        : "r"(a.x), "r"(a.y), "r"(a.z), "r"(a.w), "r"(b0), "r"(b1));
}

__device__ __forceinline__ int seg_of(const int* __restrict__ seg, int t) {
    int s = 0;
#pragma unroll
    for (int i = 1; i <= NA; i++) s += (seg[i] <= t) ? 1 : 0;
    return s < (NA - 1) ? s : (NA - 1);
}

// ===========================================================================
// Fused prepass X: reads x ONCE per 64-token strip; emits
//   (a) g_xa  : A-fragment tf32 layout [m16][k8][lane][4]
//   (b) g_Hs  : scaled LoRA h (rank 16)
//   (c) g_adp : adapter id per token
// block = 64 tokens x 256 threads; 64-col chunks staged in smem
// ===========================================================================
__global__ __launch_bounds__(256) void prep_x_kernel(
    const float* __restrict__ x, const float* __restrict__ wa,
    const float* __restrict__ scaling, const int* __restrict__ segment,
    const int* __restrict__ lora_ids)
{
    __shared__ float xs[64][68];
    __shared__ float4 was[64][4];      // wa chunk [k][rq]
    const int tid = threadIdx.x;
    const int tl = tid >> 2;           // token 0..63
    const int rq = tid & 3;            // rank quad
    const int t0 = blockIdx.x * 64;
    const int t = t0 + tl;

    const int a = lora_ids[seg_of(segment, t)];
    const int a_first = lora_ids[seg_of(segment, t0)];
    const int a_last  = lora_ids[seg_of(segment, t0 + 63)];
    const bool blk_uni = (a_first == a_last);

    // fragment-store thread mapping (fixed across chunks)
    const int ln = tid & 31;
    const int fg = ln >> 2, ft4 = ln & 3;

    float4 acc = make_float4(0.f, 0.f, 0.f, 0.f);

    for (int kc = 0; kc < D_IN; kc += 64) {
        __syncthreads();
#pragma unroll
        for (int j = 0; j < 4; j++) {
            int idx = tid + j * 256;
            int row = idx >> 4;
            int c4  = idx & 15;
            float4 v = *reinterpret_cast<const float4*>(
                x + (size_t)(t0 + row) * D_IN + kc + c4 * 4);
            *reinterpret_cast<float4*>(&xs[row][c4 * 4]) = v;
        }
        if (blk_uni) {
            int k = tid >> 2;
            int q = tid & 3;
            was[k][q] = *reinterpret_cast<const float4*>(
                wa + ((size_t)a_first * D_IN + kc + k) * RANK + q * 4);
        }
        __syncthreads();

        // ---- (a) A-fragment store: 32 blocks (4 m16 x 8 k8) x 128 floats ----
#pragma unroll
        for (int j = 0; j < 4; j++) {
            int idx = tid + j * 256;          // 0..1023
            int blk = idx >> 5;               // m16l = blk>>3, k8l = blk&7
            int lln = idx & 31;
            int g = lln >> 2, t4 = lln & 3;
            int row0 = (blk >> 3) * 16 + g;
            int col  = (blk & 7) * 8 + t4;
            uint4 o;
            o.x = f2tf(xs[row0][col]);
            o.y = f2tf(xs[row0 + 8][col]);
            o.z = f2tf(xs[row0][col + 4]);
            o.w = f2tf(xs[row0 + 8][col + 4]);
            size_t m16g = (size_t)blockIdx.x * 4 + (blk >> 3);
            size_t k8g  = (kc >> 3) + (blk & 7);
            *reinterpret_cast<uint4*>(g_xa + (m16g * 512 + k8g) * 128 + lln * 4) = o;
        }

        // ---- (b) LoRA rank-16 accumulate ----
        if (blk_uni) {
#pragma unroll 8
            for (int k = 0; k < 64; k++) {
                float4 w = was[k][rq];
                float xv = xs[tl][k];
                acc.x = fmaf(xv, w.x, acc.x);
                acc.y = fmaf(xv, w.y, acc.y);
                acc.z = fmaf(xv, w.z, acc.z);
                acc.w = fmaf(xv, w.w, acc.w);
            }
        } else {
            const float* wp = wa + (size_t)a * D_IN * RANK + (size_t)kc * RANK + rq * 4;
#pragma unroll 8
            for (int k = 0; k < 64; k++) {
                float4 w = *reinterpret_cast<const float4*>(wp + k * RANK);
                float xv = xs[tl][k];
                acc.x = fmaf(xv, w.x, acc.x);
                acc.y = fmaf(xv, w.y, acc.y);
                acc.z = fmaf(xv, w.z, acc.z);
                acc.w = fmaf(xv, w.w, acc.w);
            }
        }
    }
    const float sc = scaling[a];
    acc.x *= sc; acc.y *= sc; acc.z *= sc; acc.w *= sc;
    *reinterpret_cast<float4*>(g_Hs + (size_t)t * RANK + rq * 4) = acc;
    if (rq == 0) g_adp[t] = a;
    (void)fg; (void)ft4;
}

// ===========================================================================
// Prepass B: W -> g_wb2, RNE tf32, B-fragment layout [n8][k16][lane][4]
// ===========================================================================
__global__ __launch_bounds__(256) void perm_b_kernel(const float* __restrict__ w)
{
    __shared__ float sm[8][260];
    const int tid = threadIdx.x;
    const int k0 = blockIdx.x * 256;
    const int n0 = blockIdx.y * 8;
#pragma unroll
    for (int i = 0; i < 2; i++) {
        int idx = tid + i * 256;
        int row = idx >> 6;
        int c4  = idx & 63;
        float4 v = *reinterpret_cast<const float4*>(
            w + (size_t)(n0 + row) * D_IN + k0 + c4 * 4);
        *reinterpret_cast<float4*>(&sm[row][c4 * 4]) = v;
    }
    __syncthreads();
#pragma unroll
    for (int i = 0; i < 2; i++) {
        int idx = tid + i * 256;
        int k16 = idx >> 5;
        int ln = idx & 31;
        int g = ln >> 2, t4 = ln & 3;
        uint4 o;
        o.x = f2tf(sm[g][k16 * 16 + t4]);
        o.y = f2tf(sm[g][k16 * 16 + 4 + t4]);
        o.z = f2tf(sm[g][k16 * 16 + 8 + t4]);
        o.w = f2tf(sm[g][k16 * 16 + 12 + t4]);
        size_t off = ((size_t)blockIdx.y * 256 + blockIdx.x * 16 + k16) * 128 + ln * 4;
        *reinterpret_cast<uint4*>(g_wb2 + off) = o;
    }
}

// ===========================================================================
// Main GEMM: CTA 128x128, 4 warps (2x2) of 64x64, 3-stage cp.async,
// hoisted address math, fused bias + LoRA epilogue.  (unchanged — protected)
// ===========================================================================
__global__ __launch_bounds__(128, 2) void fused_gemm_kernel(
    const float* __restrict__ bias, const float* __restrict__ wb,
    float* __restrict__ out)
{
    extern __shared__ float smem[];
    const uint32_t sa0 = smem_u32(smem);
    const uint32_t sb0 = sa0 + STAGES * A_STAGE_B;

    const int tid  = threadIdx.x;
    const int bn   = blockIdx.x;
    const int bm   = blockIdx.y;
    const int lane = tid & 31;
    const int warp = tid >> 5;
    const int wm   = warp & 1;
    const int wn   = warp >> 1;
    const int g    = lane >> 2;
    const int t4   = lane & 3;

    int aoff[8], dAo[8], boff[8], dBo[8];
#pragma unroll
    for (int i = 0; i < 8; i++) {
        int cch = tid + i * 128;
        int blk = cch >> 5, ln = cch & 31;
        {
            int m16 = bm * 8 + (blk >> 2);
            int k8i = blk & 3;
            aoff[i] = (m16 * 512 + k8i) * 128 + ln * 4;
            dAo[i]  = blk * 512 + ln * 16;
        }
        {
            int n8  = bn * 16 + (blk >> 1);
            int k16i = blk & 1;
            boff[i] = (n8 * 256 + k16i) * 128 + ln * 4;
            dBo[i]  = blk * 512 + ln * 16;
        }
    }

    float c[4][8][4];
#pragma unroll
    for (int mi = 0; mi < 4; mi++)
#pragma unroll
        for (int ni = 0; ni < 8; ni++)
#pragma unroll
            for (int q = 0; q < 4; q++) c[mi][ni][q] = 0.f;

    auto issue_stage = [&](int kt, int s) {
        const uint32_t dA = sa0 + s * A_STAGE_B;
        const uint32_t dB = sb0 + s * B_STAGE_B;
        const int ka = kt * 512, kb = kt * 256;
#pragma unroll
        for (int i = 0; i < 8; i++)
            cp16(dA + dAo[i], g_xa + aoff[i] + ka);
#pragma unroll
        for (int i = 0; i < 8; i++)
            cp16(dB + dBo[i], g_wb2 + boff[i] + kb);
    };

    issue_stage(0, 0); CP_COMMIT();
    issue_stage(1, 1); CP_COMMIT();

    int s_cur = 0;
    for (int kt = 0; kt < KTILES; kt++) {
        CP_WAIT1();
        __syncthreads();

        if (kt + 2 < KTILES) {
            int s_next = s_cur + 2;
            if (s_next >= STAGES) s_next -= STAGES;
            issue_stage(kt + 2, s_next);
        }
        CP_COMMIT();

        const uint32_t aS = sa0 + s_cur * A_STAGE_B + wm * 8192 + lane * 16;
        const uint32_t bS = sb0 + s_cur * B_STAGE_B + wn * 8192 + lane * 16;

#pragma unroll
        for (int kp = 0; kp < 2; kp++) {
            uint4 bfr[8];
#pragma unroll
            for (int ni = 0; ni < 8; ni++)
                bfr[ni] = lds128(bS + (ni * 2 + kp) * 512);
#pragma unroll
            for (int kkh = 0; kkh < 2; kkh++) {
                const int kk = kp * 2 + kkh;
                uint4 afr[4];
#pragma unroll
                for (int mi = 0; mi < 4; mi++)
                    afr[mi] = lds128(aS + (mi * 4 + kk) * 512);
#pragma unroll
                for (int mi = 0; mi < 4; mi++)
#pragma unroll
                    for (int ni = 0; ni < 8; ni++) {
                        if (kkh == 0)
                            mma_tf32(c[mi][ni], afr[mi], bfr[ni].x, bfr[ni].y);
                        else
                            mma_tf32(c[mi][ni], afr[mi], bfr[ni].z, bfr[ni].w);
                    }
            }
        }
        s_cur = s_cur + 1; if (s_cur >= STAGES) s_cur -= STAGES;
    }

    // ---------------- epilogue: bias + LoRA + store ----------------
    const int rbase = bm * BM + wm * 64;
    const int cbase = bn * BN + wn * 64;

    int trow[8], ta[8];
#pragma unroll
    for (int mi = 0; mi < 4; mi++)
#pragma unroll
        for (int hh = 0; hh < 2; hh++) {
            int t = rbase + mi * 16 + g + 8 * hh;
            trow[mi * 2 + hh] = t;
            ta[mi * 2 + hh] = g_adp[t];
        }
    bool uni = true;
#pragma unroll
    for (int q = 1; q < 8; q++) uni = uni && (ta[q] == ta[0]);

    if (uni) {
        const float* wbp = wb + (size_t)ta[0] * RANK * D_OUT;
#pragma unroll
        for (int ni = 0; ni < 8; ni++) {
            const int o = cbase + ni * 8 + t4 * 2;
            const float2 bv = *reinterpret_cast<const float2*>(bias + o);
            float2 wv[16];
#pragma unroll
            for (int j = 0; j < 16; j++)
                wv[j] = *reinterpret_cast<const float2*>(wbp + j * D_OUT + o);
#pragma unroll
            for (int mi = 0; mi < 4; mi++)
#pragma unroll
                for (int hh = 0; hh < 2; hh++) {
                    const int t = trow[mi * 2 + hh];
                    const float4* hp = reinterpret_cast<const float4*>(g_Hs + t * RANK);
                    float hreg[16];
                    *reinterpret_cast<float4*>(&hreg[0])  = hp[0];
                    *reinterpret_cast<float4*>(&hreg[4])  = hp[1];
                    *reinterpret_cast<float4*>(&hreg[8])  = hp[2];
                    *reinterpret_cast<float4*>(&hreg[12]) = hp[3];
                    float l0 = 0.f, l1 = 0.f;
#pragma unroll
                    for (int j = 0; j < 16; j++) {
                        l0 = fmaf(hreg[j], wv[j].x, l0);
                        l1 = fmaf(hreg[j], wv[j].y, l1);
                    }
                    float2 res;
                    res.x = c[mi][ni][2 * hh + 0] + bv.x + l0;
                    res.y = c[mi][ni][2 * hh + 1] + bv.y + l1;
                    *reinterpret_cast<float2*>(out + (size_t)t * D_OUT + o) = res;
                }
        }
    } else {
#pragma unroll
        for (int q = 0; q < 8; q++) {
            const int mi = q >> 1, hh = q & 1;
            const int t = trow[q];
            const float* wbp = wb + (size_t)ta[q] * RANK * D_OUT;
            const float4* hp = reinterpret_cast<const float4*>(g_Hs + t * RANK);
            float hreg[16];
            *reinterpret_cast<float4*>(&hreg[0])  = hp[0];
            *reinterpret_cast<float4*>(&hreg[4])  = hp[1];
            *reinterpret_cast<float4*>(&hreg[8])  = hp[2];
            *reinterpret_cast<float4*>(&hreg[12]) = hp[3];
#pragma unroll
            for (int ni = 0; ni < 8; ni++) {
                const int o = cbase + ni * 8 + t4 * 2;
                float l0 = bias[o], l1 = bias[o + 1];
#pragma unroll
                for (int j = 0; j < 16; j++) {
                    l0 = fmaf(hreg[j], __ldg(wbp + j * D_OUT + o), l0);
                    l1 = fmaf(hreg[j], __ldg(wbp + j * D_OUT + o + 1), l1);
                }
                float2 res;
                res.x = c[mi][ni][2 * hh + 0] + l0;
                res.y = c[mi][ni][2 * hh + 1] + l1;
                *reinterpret_cast<float2*>(out + (size_t)t * D_OUT + o) = res;
            }
        }
    }
}

// ===========================================================================
extern "C" void kernel_launch(void* const* d_in, const int* in_sizes, int n_in,
                              void* d_out, int out_size)
{
    (void)in_sizes; (void)n_in; (void)out_size;
    const float* x       = (const float*)d_in[0];
    const float* base_w  = (const float*)d_in[1];
    const float* base_b  = (const float*)d_in[2];
    const float* wa      = (const float*)d_in[3];
    const float* wb      = (const float*)d_in[4];
    const float* scaling = (const float*)d_in[5];
    const int*   segment = (const int*)d_in[6];
    const int*   lora_id = (const int*)d_in[7];
    float* out = (float*)d_out;

    static cudaStream_t s1 = nullptr;
    static cudaEvent_t e_fork = nullptr, e1 = nullptr;
    static int inited = 0;
    if (!inited) {
        cudaStreamCreateWithFlags(&s1, cudaStreamNonBlocking);
        cudaEventCreateWithFlags(&e_fork, cudaEventDisableTiming);
        cudaEventCreateWithFlags(&e1, cudaEventDisableTiming);
        cudaFuncSetAttribute(fused_gemm_kernel,
                             cudaFuncAttributeMaxDynamicSharedMemorySize, SMEM_TOTAL);
        inited = 1;
    }

    cudaStream_t main_s = 0;
    cudaEventRecord(e_fork, main_s);
    cudaStreamWaitEvent(s1, e_fork, 0);

    prep_x_kernel<<<T_TOK / 64, 256, 0, main_s>>>(x, wa, scaling, segment, lora_id);
    perm_b_kernel<<<dim3(16, 512), 256, 0, s1>>>(base_w);

    cudaEventRecord(e1, s1);
    cudaStreamWaitEvent(main_s, e1, 0);

    dim3 grid(D_OUT / BN, T_TOK / BM);   // (32, 64)
    fused_gemm_kernel<<<grid, 128, SMEM_TOTAL, main_s>>>(base_b, wb, out);
}

// round 8
// speedup vs baseline: 1.3412x; 1.3412x over previous
#include <cuda_runtime.h>
#include <cstdint>
#include <cstddef>

#define T_TOK 8192
#define D_IN  4096
#define D_OUT 4096
#define RANK  16
#define NA    8
#define KSPLIT 4
#define KSEG  (D_IN / KSPLIT)       // 1024

// ---- GEMM tile config: CTA 128x128, 4 warps of 64x64, BK=32, 3 stages ----
#define BM 128
#define BN 128
#define BK 32
#define STAGES 3
#define KTILES (D_IN / BK)          // 128
#define A_STAGE_B 16384
#define B_STAGE_B 16384
#define SMEM_TOTAL (STAGES * (A_STAGE_B + B_STAGE_B))   // 98304

// ---- scratch (__device__ globals; no allocation allowed) ----
__device__ float g_xa[(size_t)T_TOK * D_IN];    // A-fragment order, tf32-rounded
__device__ float g_wb2[(size_t)D_OUT * D_IN];   // B-fragment order, tf32-rounded
__device__ float g_Hp[KSPLIT][T_TOK * RANK];    // unscaled partial H per k-segment
__device__ float g_Hs[T_TOK * RANK];
__device__ int   g_adp[T_TOK];

// ===========================================================================
// helpers
// ===========================================================================
__device__ __forceinline__ uint32_t smem_u32(const void* p) {
    return (uint32_t)__cvta_generic_to_shared(p);
}
__device__ __forceinline__ uint32_t f2tf(float f) {
    uint32_t u;
    asm("cvt.rna.tf32.f32 %0, %1;" : "=r"(u) : "f"(f));
    return u;
}
__device__ __forceinline__ void cp16(uint32_t dst, const void* src) {
    asm volatile("cp.async.cg.shared.global [%0], [%1], 16;\n" ::"r"(dst), "l"(src));
}
#define CP_COMMIT() asm volatile("cp.async.commit_group;\n")
#define CP_WAIT1()  asm volatile("cp.async.wait_group 1;\n")

__device__ __forceinline__ uint4 lds128(uint32_t a) {
    uint4 v;
    asm volatile("ld.shared.v4.b32 {%0,%1,%2,%3}, [%4];"
                 : "=r"(v.x), "=r"(v.y), "=r"(v.z), "=r"(v.w) : "r"(a));
    return v;
}
__device__ __forceinline__ void mma_tf32(float* c, const uint4& a, uint32_t b0, uint32_t b1) {
    asm volatile(
        "mma.sync.aligned.m16n8k8.row.col.f32.tf32.tf32.f32 "
        "{%0,%1,%2,%3},{%4,%5,%6,%7},{%8,%9},{%0,%1,%2,%3};\n"
        : "+f"(c[0]), "+f"(c[1]), "+f"(c[2]), "+f"(c[3])
        : "r"(a.x), "r"(a.y), "r"(a.z), "r"(a.w), "r"(b0), "r"(b1));
}

__device__ __forceinline__ int seg_of(const int* __restrict__ seg, int t) {
    int s = 0;
#pragma unroll
    for (int i = 1; i <= NA; i++) s += (seg[i] <= t) ? 1 : 0;
    return s < (NA - 1) ? s : (NA - 1);
}

// ===========================================================================
// Prepass A: x -> g_xa, RNE tf32, A-fragment layout [m16][k8][lane][4]
// ===========================================================================
__global__ __launch_bounds__(256) void perm_a_kernel(const float* __restrict__ x)
{
    __shared__ float sm[16][132];
    const int tid = threadIdx.x;
    const int k0 = blockIdx.x * 128;
    const int m0 = blockIdx.y * 16;
#pragma unroll
    for (int i = 0; i < 2; i++) {
        int idx = tid + i * 256;
        int row = idx >> 5;
        int c4  = idx & 31;
        float4 v = *reinterpret_cast<const float4*>(
            x + (size_t)(m0 + row) * D_IN + k0 + c4 * 4);
        *reinterpret_cast<float4*>(&sm[row][c4 * 4]) = v;
    }
    __syncthreads();
#pragma unroll
    for (int i = 0; i < 2; i++) {
        int idx = tid + i * 256;
        int k8 = idx >> 5;
        int ln = idx & 31;
        int g = ln >> 2, t4 = ln & 3;
        uint4 o;
        o.x = f2tf(sm[g][k8 * 8 + t4]);
        o.y = f2tf(sm[g + 8][k8 * 8 + t4]);
        o.z = f2tf(sm[g][k8 * 8 + 4 + t4]);
        o.w = f2tf(sm[g + 8][k8 * 8 + 4 + t4]);
        size_t off = ((size_t)blockIdx.y * 512 + blockIdx.x * 16 + k8) * 128 + ln * 4;
        *reinterpret_cast<uint4*>(g_xa + off) = o;
    }
}

// ===========================================================================
// Prepass B: W -> g_wb2, RNE tf32, B-fragment layout [n8][k16][lane][4]
// ===========================================================================
__global__ __launch_bounds__(256) void perm_b_kernel(const float* __restrict__ w)
{
    __shared__ float sm[8][260];
    const int tid = threadIdx.x;
    const int k0 = blockIdx.x * 256;
    const int n0 = blockIdx.y * 8;
#pragma unroll
    for (int i = 0; i < 2; i++) {
        int idx = tid + i * 256;
        int row = idx >> 6;
        int c4  = idx & 63;
        float4 v = *reinterpret_cast<const float4*>(
            w + (size_t)(n0 + row) * D_IN + k0 + c4 * 4);
        *reinterpret_cast<float4*>(&sm[row][c4 * 4]) = v;
    }
    __syncthreads();
#pragma unroll
    for (int i = 0; i < 2; i++) {
        int idx = tid + i * 256;
        int k16 = idx >> 5;
        int ln = idx & 31;
        int g = ln >> 2, t4 = ln & 3;
        uint4 o;
        o.x = f2tf(sm[g][k16 * 16 + t4]);
        o.y = f2tf(sm[g][k16 * 16 + 4 + t4]);
        o.z = f2tf(sm[g][k16 * 16 + 8 + t4]);
        o.w = f2tf(sm[g][k16 * 16 + 12 + t4]);
        size_t off = ((size_t)blockIdx.y * 256 + blockIdx.x * 16 + k16) * 128 + ln * 4;
        *reinterpret_cast<uint4*>(g_wb2 + off) = o;
    }
}

// ===========================================================================
// LoRA H partial: block (bx: 64 tokens, by: k-segment of 1024)
// writes UNSCALED partial sums to g_Hp[by]; g_adp from by==0
// ===========================================================================
__global__ __launch_bounds__(256) void lora_part_kernel(
    const float* __restrict__ x, const float* __restrict__ wa,
    const int* __restrict__ segment, const int* __restrict__ lora_ids)
{
    __shared__ float xs[64][68];
    __shared__ float4 was[64][4];
    const int tid = threadIdx.x;
    const int tl = tid >> 2;
    const int rq = tid & 3;
    const int t0 = blockIdx.x * 64;
    const int kp = blockIdx.y;
    const int kbase = kp * KSEG;
    const int t = t0 + tl;

    const int a = lora_ids[seg_of(segment, t)];
    const int a_first = lora_ids[seg_of(segment, t0)];
    const int a_last  = lora_ids[seg_of(segment, t0 + 63)];
    const bool blk_uni = (a_first == a_last);

    float4 acc = make_float4(0.f, 0.f, 0.f, 0.f);

    for (int kc = kbase; kc < kbase + KSEG; kc += 64) {
        __syncthreads();
#pragma unroll
        for (int j = 0; j < 4; j++) {
            int idx = tid + j * 256;
            int row = idx >> 4;
            int c4  = idx & 15;
            float4 v = *reinterpret_cast<const float4*>(
                x + (size_t)(t0 + row) * D_IN + kc + c4 * 4);
            *reinterpret_cast<float4*>(&xs[row][c4 * 4]) = v;
        }
        if (blk_uni) {
            int k = tid >> 2;
            int q = tid & 3;
            was[k][q] = *reinterpret_cast<const float4*>(
                wa + ((size_t)a_first * D_IN + kc + k) * RANK + q * 4);
        }
        __syncthreads();

        if (blk_uni) {
#pragma unroll 8
            for (int k = 0; k < 64; k++) {
                float4 w = was[k][rq];
                float xv = xs[tl][k];
                acc.x = fmaf(xv, w.x, acc.x);
                acc.y = fmaf(xv, w.y, acc.y);
                acc.z = fmaf(xv, w.z, acc.z);
                acc.w = fmaf(xv, w.w, acc.w);
            }
        } else {
            const float* wp = wa + (size_t)a * D_IN * RANK + (size_t)kc * RANK + rq * 4;
#pragma unroll 8
            for (int k = 0; k < 64; k++) {
                float4 w = *reinterpret_cast<const float4*>(wp + k * RANK);
                float xv = xs[tl][k];
                acc.x = fmaf(xv, w.x, acc.x);
                acc.y = fmaf(xv, w.y, acc.y);
                acc.z = fmaf(xv, w.z, acc.z);
                acc.w = fmaf(xv, w.w, acc.w);
            }
        }
    }
    *reinterpret_cast<float4*>(&g_Hp[kp][(size_t)t * RANK + rq * 4]) = acc;
    if (kp == 0 && rq == 0) g_adp[t] = a;
}

// ===========================================================================
// Combine: g_Hs = scaling[adp] * (p0 + p1 + p2 + p3), fixed order (deterministic)
// ===========================================================================
__global__ __launch_bounds__(256) void lora_combine_kernel(
    const float* __restrict__ scaling)
{
    const int idx = blockIdx.x * 256 + threadIdx.x;   // 0 .. T*RANK/4-1
    const int t = idx >> 2;
    const float sc = scaling[g_adp[t]];
    float4 p0 = *reinterpret_cast<const float4*>(&g_Hp[0][idx * 4]);
    float4 p1 = *reinterpret_cast<const float4*>(&g_Hp[1][idx * 4]);
    float4 p2 = *reinterpret_cast<const float4*>(&g_Hp[2][idx * 4]);
    float4 p3 = *reinterpret_cast<const float4*>(&g_Hp[3][idx * 4]);
    float4 r;
    r.x = ((p0.x + p1.x) + (p2.x + p3.x)) * sc;
    r.y = ((p0.y + p1.y) + (p2.y + p3.y)) * sc;
    r.z = ((p0.z + p1.z) + (p2.z + p3.z)) * sc;
    r.w = ((p0.w + p1.w) + (p2.w + p3.w)) * sc;
    *reinterpret_cast<float4*>(&g_Hs[idx * 4]) = r;
}

// ===========================================================================
// Main GEMM: CTA 128x128, 4 warps (2x2) of 64x64, 3-stage cp.async,
// hoisted address math, fused bias + LoRA epilogue.  (unchanged — protected)
// ===========================================================================
__global__ __launch_bounds__(128, 2) void fused_gemm_kernel(
    const float* __restrict__ bias, const float* __restrict__ wb,
    float* __restrict__ out)
{
    extern __shared__ float smem[];
    const uint32_t sa0 = smem_u32(smem);
    const uint32_t sb0 = sa0 + STAGES * A_STAGE_B;

    const int tid  = threadIdx.x;
    const int bn   = blockIdx.x;
    const int bm   = blockIdx.y;
    const int lane = tid & 31;
    const int warp = tid >> 5;
    const int wm   = warp & 1;
    const int wn   = warp >> 1;
    const int g    = lane >> 2;
    const int t4   = lane & 3;

    int aoff[8], dAo[8], boff[8], dBo[8];
#pragma unroll
    for (int i = 0; i < 8; i++) {
        int cch = tid + i * 128;
        int blk = cch >> 5, ln = cch & 31;
        {
            int m16 = bm * 8 + (blk >> 2);
            int k8i = blk & 3;
            aoff[i] = (m16 * 512 + k8i) * 128 + ln * 4;
            dAo[i]  = blk * 512 + ln * 16;
        }
        {
            int n8  = bn * 16 + (blk >> 1);
            int k16i = blk & 1;
            boff[i] = (n8 * 256 + k16i) * 128 + ln * 4;
            dBo[i]  = blk * 512 + ln * 16;
        }
    }

    float c[4][8][4];
#pragma unroll
    for (int mi = 0; mi < 4; mi++)
#pragma unroll
        for (int ni = 0; ni < 8; ni++)
#pragma unroll
            for (int q = 0; q < 4; q++) c[mi][ni][q] = 0.f;

    auto issue_stage = [&](int kt, int s) {
        const uint32_t dA = sa0 + s * A_STAGE_B;
        const uint32_t dB = sb0 + s * B_STAGE_B;
        const int ka = kt * 512, kb = kt * 256;
#pragma unroll
        for (int i = 0; i < 8; i++)
            cp16(dA + dAo[i], g_xa + aoff[i] + ka);
#pragma unroll
        for (int i = 0; i < 8; i++)
            cp16(dB + dBo[i], g_wb2 + boff[i] + kb);
    };

    issue_stage(0, 0); CP_COMMIT();
    issue_stage(1, 1); CP_COMMIT();

    int s_cur = 0;
    for (int kt = 0; kt < KTILES; kt++) {
        CP_WAIT1();
        __syncthreads();

        if (kt + 2 < KTILES) {
            int s_next = s_cur + 2;
            if (s_next >= STAGES) s_next -= STAGES;
            issue_stage(kt + 2, s_next);
        }
        CP_COMMIT();

        const uint32_t aS = sa0 + s_cur * A_STAGE_B + wm * 8192 + lane * 16;
        const uint32_t bS = sb0 + s_cur * B_STAGE_B + wn * 8192 + lane * 16;

#pragma unroll
        for (int kp = 0; kp < 2; kp++) {
            uint4 bfr[8];
#pragma unroll
            for (int ni = 0; ni < 8; ni++)
                bfr[ni] = lds128(bS + (ni * 2 + kp) * 512);
#pragma unroll
            for (int kkh = 0; kkh < 2; kkh++) {
                const int kk = kp * 2 + kkh;
                uint4 afr[4];
#pragma unroll
                for (int mi = 0; mi < 4; mi++)
                    afr[mi] = lds128(aS + (mi * 4 + kk) * 512);
#pragma unroll
                for (int mi = 0; mi < 4; mi++)
#pragma unroll
                    for (int ni = 0; ni < 8; ni++) {
                        if (kkh == 0)
                            mma_tf32(c[mi][ni], afr[mi], bfr[ni].x, bfr[ni].y);
                        else
                            mma_tf32(c[mi][ni], afr[mi], bfr[ni].z, bfr[ni].w);
                    }
            }
        }
        s_cur = s_cur + 1; if (s_cur >= STAGES) s_cur -= STAGES;
    }

    // ---------------- epilogue: bias + LoRA + store ----------------
    const int rbase = bm * BM + wm * 64;
    const int cbase = bn * BN + wn * 64;

    int trow[8], ta[8];
#pragma unroll
    for (int mi = 0; mi < 4; mi++)
#pragma unroll
        for (int hh = 0; hh < 2; hh++) {
            int t = rbase + mi * 16 + g + 8 * hh;
            trow[mi * 2 + hh] = t;
            ta[mi * 2 + hh] = g_adp[t];
        }
    bool uni = true;
#pragma unroll
    for (int q = 1; q < 8; q++) uni = uni && (ta[q] == ta[0]);

    if (uni) {
        const float* wbp = wb + (size_t)ta[0] * RANK * D_OUT;
#pragma unroll
        for (int ni = 0; ni < 8; ni++) {
            const int o = cbase + ni * 8 + t4 * 2;
            const float2 bv = *reinterpret_cast<const float2*>(bias + o);
            float2 wv[16];
#pragma unroll
            for (int j = 0; j < 16; j++)
                wv[j] = *reinterpret_cast<const float2*>(wbp + j * D_OUT + o);
#pragma unroll
            for (int mi = 0; mi < 4; mi++)
#pragma unroll
                for (int hh = 0; hh < 2; hh++) {
                    const int t = trow[mi * 2 + hh];
                    const float4* hp = reinterpret_cast<const float4*>(g_Hs + t * RANK);
                    float hreg[16];
                    *reinterpret_cast<float4*>(&hreg[0])  = hp[0];
                    *reinterpret_cast<float4*>(&hreg[4])  = hp[1];
                    *reinterpret_cast<float4*>(&hreg[8])  = hp[2];
                    *reinterpret_cast<float4*>(&hreg[12]) = hp[3];
                    float l0 = 0.f, l1 = 0.f;
#pragma unroll
                    for (int j = 0; j < 16; j++) {
                        l0 = fmaf(hreg[j], wv[j].x, l0);
                        l1 = fmaf(hreg[j], wv[j].y, l1);
                    }
                    float2 res;
                    res.x = c[mi][ni][2 * hh + 0] + bv.x + l0;
                    res.y = c[mi][ni][2 * hh + 1] + bv.y + l1;
                    *reinterpret_cast<float2*>(out + (size_t)t * D_OUT + o) = res;
                }
        }
    } else {
#pragma unroll
        for (int q = 0; q < 8; q++) {
            const int mi = q >> 1, hh = q & 1;
            const int t = trow[q];
            const float* wbp = wb + (size_t)ta[q] * RANK * D_OUT;
            const float4* hp = reinterpret_cast<const float4*>(g_Hs + t * RANK);
            float hreg[16];
            *reinterpret_cast<float4*>(&hreg[0])  = hp[0];
            *reinterpret_cast<float4*>(&hreg[4])  = hp[1];
            *reinterpret_cast<float4*>(&hreg[8])  = hp[2];
            *reinterpret_cast<float4*>(&hreg[12]) = hp[3];
#pragma unroll
            for (int ni = 0; ni < 8; ni++) {
                const int o = cbase + ni * 8 + t4 * 2;
                float l0 = bias[o], l1 = bias[o + 1];
#pragma unroll
                for (int j = 0; j < 16; j++) {
                    l0 = fmaf(hreg[j], __ldg(wbp + j * D_OUT + o), l0);
                    l1 = fmaf(hreg[j], __ldg(wbp + j * D_OUT + o + 1), l1);
                }
                float2 res;
                res.x = c[mi][ni][2 * hh + 0] + l0;
                res.y = c[mi][ni][2 * hh + 1] + l1;
                *reinterpret_cast<float2*>(out + (size_t)t * D_OUT + o) = res;
            }
        }
    }
}

// ===========================================================================
extern "C" void kernel_launch(void* const* d_in, const int* in_sizes, int n_in,
                              void* d_out, int out_size)
{
    (void)in_sizes; (void)n_in; (void)out_size;
    const float* x       = (const float*)d_in[0];
    const float* base_w  = (const float*)d_in[1];
    const float* base_b  = (const float*)d_in[2];
    const float* wa      = (const float*)d_in[3];
    const float* wb      = (const float*)d_in[4];
    const float* scaling = (const float*)d_in[5];
    const int*   segment = (const int*)d_in[6];
    const int*   lora_id = (const int*)d_in[7];
    float* out = (float*)d_out;

    static cudaStream_t s1 = nullptr, s2 = nullptr;
    static cudaEvent_t e_fork = nullptr, e1 = nullptr, e2 = nullptr;
    static int inited = 0;
    if (!inited) {
        cudaStreamCreateWithFlags(&s1, cudaStreamNonBlocking);
        cudaStreamCreateWithFlags(&s2, cudaStreamNonBlocking);
        cudaEventCreateWithFlags(&e_fork, cudaEventDisableTiming);
        cudaEventCreateWithFlags(&e1, cudaEventDisableTiming);
        cudaEventCreateWithFlags(&e2, cudaEventDisableTiming);
        cudaFuncSetAttribute(fused_gemm_kernel,
                             cudaFuncAttributeMaxDynamicSharedMemorySize, SMEM_TOTAL);
        inited = 1;
    }

    cudaStream_t main_s = 0;
    cudaEventRecord(e_fork, main_s);
    cudaStreamWaitEvent(s1, e_fork, 0);
    cudaStreamWaitEvent(s2, e_fork, 0);

    perm_a_kernel<<<dim3(32, 512), 256, 0, main_s>>>(x);
    perm_b_kernel<<<dim3(16, 512), 256, 0, s1>>>(base_w);
    lora_part_kernel<<<dim3(T_TOK / 64, KSPLIT), 256, 0, s2>>>(x, wa, segment, lora_id);
    lora_combine_kernel<<<T_TOK * RANK / 4 / 256, 256, 0, s2>>>(scaling);

    cudaEventRecord(e1, s1);
    cudaEventRecord(e2, s2);
    cudaStreamWaitEvent(main_s, e1, 0);
    cudaStreamWaitEvent(main_s, e2, 0);

    dim3 grid(D_OUT / BN, T_TOK / BM);   // (32, 64)
    fused_gemm_kernel<<<grid, 128, SMEM_TOTAL, main_s>>>(base_b, wb, out);
}

// round 9
// speedup vs baseline: 1.4003x; 1.0441x over previous
#include <cuda_runtime.h>
#include <cstdint>
#include <cstddef>

#define T_TOK 8192
#define D_IN  4096
#define D_OUT 4096
#define RANK  16
#define NA    8
#define KSPLIT 8
#define KSEG  (D_IN / KSPLIT)       // 512

// ---- GEMM tile config: CTA 128x128, 4 warps of 64x64, BK=32, 3 stages ----
#define BM 128
#define BN 128
#define BK 32
#define STAGES 3
#define KTILES (D_IN / BK)          // 128
#define A_STAGE_B 16384
#define B_STAGE_B 16384
#define SMEM_TOTAL (STAGES * (A_STAGE_B + B_STAGE_B))   // 98304

// ---- scratch (__device__ globals; no allocation allowed) ----
__device__ float g_xa[(size_t)T_TOK * D_IN];    // A-fragment order, tf32-rounded
__device__ float g_wb2[(size_t)D_OUT * D_IN];   // B-fragment order, tf32-rounded
__device__ float g_Hp[KSPLIT][T_TOK * RANK];    // unscaled partial H per k-segment
__device__ float g_Hs[T_TOK * RANK];
__device__ int   g_adp[T_TOK];

// ===========================================================================
// helpers
// ===========================================================================
__device__ __forceinline__ uint32_t smem_u32(const void* p) {
    return (uint32_t)__cvta_generic_to_shared(p);
}
__device__ __forceinline__ uint32_t f2tf(float f) {
    uint32_t u;
    asm("cvt.rna.tf32.f32 %0, %1;" : "=r"(u) : "f"(f));
    return u;
}
__device__ __forceinline__ void cp16(uint32_t dst, const void* src) {
    asm volatile("cp.async.cg.shared.global [%0], [%1], 16;\n" ::"r"(dst), "l"(src));
}
#define CP_COMMIT() asm volatile("cp.async.commit_group;\n")
#define CP_WAIT1()  asm volatile("cp.async.wait_group 1;\n")

__device__ __forceinline__ uint4 lds128(uint32_t a) {
    uint4 v;
    asm volatile("ld.shared.v4.b32 {%0,%1,%2,%3}, [%4];"
                 : "=r"(v.x), "=r"(v.y), "=r"(v.z), "=r"(v.w) : "r"(a));
    return v;
}
__device__ __forceinline__ void mma_tf32(float* c, const uint4& a, uint32_t b0, uint32_t b1) {
    asm volatile(
        "mma.sync.aligned.m16n8k8.row.col.f32.tf32.tf32.f32 "
        "{%0,%1,%2,%3},{%4,%5,%6,%7},{%8,%9},{%0,%1,%2,%3};\n"
        : "+f"(c[0]), "+f"(c[1]), "+f"(c[2]), "+f"(c[3])
        : "r"(a.x), "r"(a.y), "r"(a.z), "r"(a.w), "r"(b0), "r"(b1));
}

__device__ __forceinline__ int seg_of(const int* __restrict__ seg, int t) {
    int s = 0;
#pragma unroll
    for (int i = 1; i <= NA; i++) s += (seg[i] <= t) ? 1 : 0;
    return s < (NA - 1) ? s : (NA - 1);
}

// ===========================================================================
// Fused prepass X: block (bx=kseg 0..7, by=token strip 0..127)
// Reads its 64-token x 512-k x-block ONCE; emits
//   (a) g_xa A-fragments (tf32 RNE) for this region
//   (b) g_Hp[kseg] unscaled LoRA partial (rank 16)
//   (c) g_adp (kseg 0 only)
// 8 serial chunks of 64x64 per block; 1024 blocks total.
// ===========================================================================
__global__ __launch_bounds__(256) void prep_x_kernel(
    const float* __restrict__ x, const float* __restrict__ wa,
    const int* __restrict__ segment, const int* __restrict__ lora_ids)
{
    __shared__ float xs[64][68];
    __shared__ float4 was[64][4];
    const int tid = threadIdx.x;
    const int tl = tid >> 2;           // token 0..63
    const int rq = tid & 3;            // rank quad
    const int kp = blockIdx.x;         // kseg
    const int kbase = kp * KSEG;
    const int t0 = blockIdx.y * 64;
    const int t = t0 + tl;

    const int a = lora_ids[seg_of(segment, t)];
    const int a_first = lora_ids[seg_of(segment, t0)];
    const int a_last  = lora_ids[seg_of(segment, t0 + 63)];
    const bool blk_uni = (a_first == a_last);

    float4 acc = make_float4(0.f, 0.f, 0.f, 0.f);

    for (int ci = 0; ci < KSEG / 64; ci++) {
        const int kc = kbase + ci * 64;
        __syncthreads();
#pragma unroll
        for (int j = 0; j < 4; j++) {
            int idx = tid + j * 256;
            int row = idx >> 4;
            int c4  = idx & 15;
            float4 v = *reinterpret_cast<const float4*>(
                x + (size_t)(t0 + row) * D_IN + kc + c4 * 4);
            *reinterpret_cast<float4*>(&xs[row][c4 * 4]) = v;
        }
        if (blk_uni) {
            int k = tid >> 2;
            int q = tid & 3;
            was[k][q] = *reinterpret_cast<const float4*>(
                wa + ((size_t)a_first * D_IN + kc + k) * RANK + q * 4);
        }
        __syncthreads();

        // ---- (a) A-fragment emit: 32 blocks (4 m16 x 8 k8) x 128 floats ----
#pragma unroll
        for (int j = 0; j < 4; j++) {
            int idx = tid + j * 256;          // 0..1023
            int blk = idx >> 5;               // 0..31
            int lln = idx & 31;
            int g = lln >> 2, t4 = lln & 3;
            int row0 = (blk >> 3) * 16 + g;
            int col  = (blk & 7) * 8 + t4;
            uint4 o;
            o.x = f2tf(xs[row0][col]);
            o.y = f2tf(xs[row0 + 8][col]);
            o.z = f2tf(xs[row0][col + 4]);
            o.w = f2tf(xs[row0 + 8][col + 4]);
            size_t m16g = (size_t)blockIdx.y * 4 + (blk >> 3);
            size_t k8g  = (size_t)(kc >> 3) + (blk & 7);
            *reinterpret_cast<uint4*>(g_xa + (m16g * 512 + k8g) * 128 + lln * 4) = o;
        }

        // ---- (b) LoRA rank-16 accumulate over this 64-k chunk ----
        if (blk_uni) {
#pragma unroll 8
            for (int k = 0; k < 64; k++) {
                float4 w = was[k][rq];
                float xv = xs[tl][k];
                acc.x = fmaf(xv, w.x, acc.x);
                acc.y = fmaf(xv, w.y, acc.y);
                acc.z = fmaf(xv, w.z, acc.z);
                acc.w = fmaf(xv, w.w, acc.w);
            }
        } else {
            const float* wp = wa + (size_t)a * D_IN * RANK + (size_t)kc * RANK + rq * 4;
#pragma unroll 8
            for (int k = 0; k < 64; k++) {
                float4 w = *reinterpret_cast<const float4*>(wp + k * RANK);
                float xv = xs[tl][k];
                acc.x = fmaf(xv, w.x, acc.x);
                acc.y = fmaf(xv, w.y, acc.y);
                acc.z = fmaf(xv, w.z, acc.z);
                acc.w = fmaf(xv, w.w, acc.w);
            }
        }
    }
    *reinterpret_cast<float4*>(&g_Hp[kp][(size_t)t * RANK + rq * 4]) = acc;
    if (kp == 0 && rq == 0) g_adp[t] = a;
}

// ===========================================================================
// Combine: g_Hs = scaling[adp] * sum of 8 partials, fixed order (deterministic)
// ===========================================================================
__global__ __launch_bounds__(256) void lora_combine_kernel(
    const float* __restrict__ scaling)
{
    const int idx = blockIdx.x * 256 + threadIdx.x;   // 0 .. T*RANK/4-1
    const int t = idx >> 2;
    const float sc = scaling[g_adp[t]];
    float4 s01, s23, s45, s67;
    {
        float4 p0 = *reinterpret_cast<const float4*>(&g_Hp[0][idx * 4]);
        float4 p1 = *reinterpret_cast<const float4*>(&g_Hp[1][idx * 4]);
        s01.x = p0.x + p1.x; s01.y = p0.y + p1.y; s01.z = p0.z + p1.z; s01.w = p0.w + p1.w;
    }
    {
        float4 p2 = *reinterpret_cast<const float4*>(&g_Hp[2][idx * 4]);
        float4 p3 = *reinterpret_cast<const float4*>(&g_Hp[3][idx * 4]);
        s23.x = p2.x + p3.x; s23.y = p2.y + p3.y; s23.z = p2.z + p3.z; s23.w = p2.w + p3.w;
    }
    {
        float4 p4 = *reinterpret_cast<const float4*>(&g_Hp[4][idx * 4]);
        float4 p5 = *reinterpret_cast<const float4*>(&g_Hp[5][idx * 4]);
        s45.x = p4.x + p5.x; s45.y = p4.y + p5.y; s45.z = p4.z + p5.z; s45.w = p4.w + p5.w;
    }
    {
        float4 p6 = *reinterpret_cast<const float4*>(&g_Hp[6][idx * 4]);
        float4 p7 = *reinterpret_cast<const float4*>(&g_Hp[7][idx * 4]);
        s67.x = p6.x + p7.x; s67.y = p6.y + p7.y; s67.z = p6.z + p7.z; s67.w = p6.w + p7.w;
    }
    float4 r;
    r.x = ((s01.x + s23.x) + (s45.x + s67.x)) * sc;
    r.y = ((s01.y + s23.y) + (s45.y + s67.y)) * sc;
    r.z = ((s01.z + s23.z) + (s45.z + s67.z)) * sc;
    r.w = ((s01.w + s23.w) + (s45.w + s67.w)) * sc;
    *reinterpret_cast<float4*>(&g_Hs[idx * 4]) = r;
}

// ===========================================================================
// Prepass B: W -> g_wb2, RNE tf32, B-fragment layout [n8][k16][lane][4]
// ===========================================================================
__global__ __launch_bounds__(256) void perm_b_kernel(const float* __restrict__ w)
{
    __shared__ float sm[8][260];
    const int tid = threadIdx.x;
    const int k0 = blockIdx.x * 256;
    const int n0 = blockIdx.y * 8;
#pragma unroll
    for (int i = 0; i < 2; i++) {
        int idx = tid + i * 256;
        int row = idx >> 6;
        int c4  = idx & 63;
        float4 v = *reinterpret_cast<const float4*>(
            w + (size_t)(n0 + row) * D_IN + k0 + c4 * 4);
        *reinterpret_cast<float4*>(&sm[row][c4 * 4]) = v;
    }
    __syncthreads();
#pragma unroll
    for (int i = 0; i < 2; i++) {
        int idx = tid + i * 256;
        int k16 = idx >> 5;
        int ln = idx & 31;
        int g = ln >> 2, t4 = ln & 3;
        uint4 o;
        o.x = f2tf(sm[g][k16 * 16 + t4]);
        o.y = f2tf(sm[g][k16 * 16 + 4 + t4]);
        o.z = f2tf(sm[g][k16 * 16 + 8 + t4]);
        o.w = f2tf(sm[g][k16 * 16 + 12 + t4]);
        size_t off = ((size_t)blockIdx.y * 256 + blockIdx.x * 16 + k16) * 128 + ln * 4;
        *reinterpret_cast<uint4*>(g_wb2 + off) = o;
    }
}

// ===========================================================================
// Main GEMM: CTA 128x128, 4 warps (2x2) of 64x64, 3-stage cp.async.
// Mainloop reorder: first fragment loads BEFORE next-stage cp.async issue.
// ===========================================================================
__global__ __launch_bounds__(128, 2) void fused_gemm_kernel(
    const float* __restrict__ bias, const float* __restrict__ wb,
    float* __restrict__ out)
{
    extern __shared__ float smem[];
    const uint32_t sa0 = smem_u32(smem);
    const uint32_t sb0 = sa0 + STAGES * A_STAGE_B;

    const int tid  = threadIdx.x;
    const int bn   = blockIdx.x;
    const int bm   = blockIdx.y;
    const int lane = tid & 31;
    const int warp = tid >> 5;
    const int wm   = warp & 1;
    const int wn   = warp >> 1;
    const int g    = lane >> 2;
    const int t4   = lane & 3;

    int aoff[8], dAo[8], boff[8], dBo[8];
#pragma unroll
    for (int i = 0; i < 8; i++) {
        int cch = tid + i * 128;
        int blk = cch >> 5, ln = cch & 31;
        {
            int m16 = bm * 8 + (blk >> 2);
            int k8i = blk & 3;
            aoff[i] = (m16 * 512 + k8i) * 128 + ln * 4;
            dAo[i]  = blk * 512 + ln * 16;
        }
        {
            int n8  = bn * 16 + (blk >> 1);
            int k16i = blk & 1;
            boff[i] = (n8 * 256 + k16i) * 128 + ln * 4;
            dBo[i]  = blk * 512 + ln * 16;
        }
    }

    float c[4][8][4];
#pragma unroll
    for (int mi = 0; mi < 4; mi++)
#pragma unroll
        for (int ni = 0; ni < 8; ni++)
#pragma unroll
            for (int q = 0; q < 4; q++) c[mi][ni][q] = 0.f;

    auto issue_stage = [&](int kt, int s) {
        const uint32_t dA = sa0 + s * A_STAGE_B;
        const uint32_t dB = sb0 + s * B_STAGE_B;
        const int ka = kt * 512, kb = kt * 256;
#pragma unroll
        for (int i = 0; i < 8; i++)
            cp16(dA + dAo[i], g_xa + aoff[i] + ka);
#pragma unroll
        for (int i = 0; i < 8; i++)
            cp16(dB + dBo[i], g_wb2 + boff[i] + kb);
    };

    issue_stage(0, 0); CP_COMMIT();
    issue_stage(1, 1); CP_COMMIT();

    int s_cur = 0;
    for (int kt = 0; kt < KTILES; kt++) {
        CP_WAIT1();
        __syncthreads();

        const uint32_t aS = sa0 + s_cur * A_STAGE_B + wm * 8192 + lane * 16;
        const uint32_t bS = sb0 + s_cur * B_STAGE_B + wn * 8192 + lane * 16;

        // start critical fragment loads first (kp=0)
        uint4 bfr[8];
#pragma unroll
        for (int ni = 0; ni < 8; ni++)
            bfr[ni] = lds128(bS + (ni * 2) * 512);
        uint4 afr[4];
#pragma unroll
        for (int mi = 0; mi < 4; mi++)
            afr[mi] = lds128(aS + (mi * 4) * 512);

        // then issue next stage's async copies
        if (kt + 2 < KTILES) {
            int s_next = s_cur + 2;
            if (s_next >= STAGES) s_next -= STAGES;
            issue_stage(kt + 2, s_next);
        }
        CP_COMMIT();

        // kp = 0, kkh = 0
#pragma unroll
        for (int mi = 0; mi < 4; mi++)
#pragma unroll
            for (int ni = 0; ni < 8; ni++)
                mma_tf32(c[mi][ni], afr[mi], bfr[ni].x, bfr[ni].y);
        // kp = 0, kkh = 1
#pragma unroll
        for (int mi = 0; mi < 4; mi++)
            afr[mi] = lds128(aS + (mi * 4 + 1) * 512);
#pragma unroll
        for (int mi = 0; mi < 4; mi++)
#pragma unroll
            for (int ni = 0; ni < 8; ni++)
                mma_tf32(c[mi][ni], afr[mi], bfr[ni].z, bfr[ni].w);

        // kp = 1
#pragma unroll
        for (int ni = 0; ni < 8; ni++)
            bfr[ni] = lds128(bS + (ni * 2 + 1) * 512);
#pragma unroll
        for (int mi = 0; mi < 4; mi++)
            afr[mi] = lds128(aS + (mi * 4 + 2) * 512);
#pragma unroll
        for (int mi = 0; mi < 4; mi++)
#pragma unroll
            for (int ni = 0; ni < 8; ni++)
                mma_tf32(c[mi][ni], afr[mi], bfr[ni].x, bfr[ni].y);
#pragma unroll
        for (int mi = 0; mi < 4; mi++)
            afr[mi] = lds128(aS + (mi * 4 + 3) * 512);
#pragma unroll
        for (int mi = 0; mi < 4; mi++)
#pragma unroll
            for (int ni = 0; ni < 8; ni++)
                mma_tf32(c[mi][ni], afr[mi], bfr[ni].z, bfr[ni].w);

        s_cur = s_cur + 1; if (s_cur >= STAGES) s_cur -= STAGES;
    }

    // ---------------- epilogue: bias + LoRA + store ----------------
    const int rbase = bm * BM + wm * 64;
    const int cbase = bn * BN + wn * 64;

    int trow[8], ta[8];
#pragma unroll
    for (int mi = 0; mi < 4; mi++)
#pragma unroll
        for (int hh = 0; hh < 2; hh++) {
            int t = rbase + mi * 16 + g + 8 * hh;
            trow[mi * 2 + hh] = t;
            ta[mi * 2 + hh] = g_adp[t];
        }
    bool uni = true;
#pragma unroll
    for (int q = 1; q < 8; q++) uni = uni && (ta[q] == ta[0]);

    if (uni) {
        const float* wbp = wb + (size_t)ta[0] * RANK * D_OUT;
#pragma unroll
        for (int ni = 0; ni < 8; ni++) {
            const int o = cbase + ni * 8 + t4 * 2;
            const float2 bv = *reinterpret_cast<const float2*>(bias + o);
            float2 wv[16];
#pragma unroll
            for (int j = 0; j < 16; j++)
                wv[j] = *reinterpret_cast<const float2*>(wbp + j * D_OUT + o);
#pragma unroll
            for (int mi = 0; mi < 4; mi++)
#pragma unroll
                for (int hh = 0; hh < 2; hh++) {
                    const int t = trow[mi * 2 + hh];
                    const float4* hp = reinterpret_cast<const float4*>(g_Hs + t * RANK);
                    float hreg[16];
                    *reinterpret_cast<float4*>(&hreg[0])  = hp[0];
                    *reinterpret_cast<float4*>(&hreg[4])  = hp[1];
                    *reinterpret_cast<float4*>(&hreg[8])  = hp[2];
                    *reinterpret_cast<float4*>(&hreg[12]) = hp[3];
                    float l0 = 0.f, l1 = 0.f;
#pragma unroll
                    for (int j = 0; j < 16; j++) {
                        l0 = fmaf(hreg[j], wv[j].x, l0);
                        l1 = fmaf(hreg[j], wv[j].y, l1);
                    }
                    float2 res;
                    res.x = c[mi][ni][2 * hh + 0] + bv.x + l0;
                    res.y = c[mi][ni][2 * hh + 1] + bv.y + l1;
                    *reinterpret_cast<float2*>(out + (size_t)t * D_OUT + o) = res;
                }
        }
    } else {
#pragma unroll
        for (int q = 0; q < 8; q++) {
            const int mi = q >> 1, hh = q & 1;
            const int t = trow[q];
            const float* wbp = wb + (size_t)ta[q] * RANK * D_OUT;
            const float4* hp = reinterpret_cast<const float4*>(g_Hs + t * RANK);
            float hreg[16];
            *reinterpret_cast<float4*>(&hreg[0])  = hp[0];
            *reinterpret_cast<float4*>(&hreg[4])  = hp[1];
            *reinterpret_cast<float4*>(&hreg[8])  = hp[2];
            *reinterpret_cast<float4*>(&hreg[12]) = hp[3];
#pragma unroll
            for (int ni = 0; ni < 8; ni++) {
                const int o = cbase + ni * 8 + t4 * 2;
                float l0 = bias[o], l1 = bias[o + 1];
#pragma unroll
                for (int j = 0; j < 16; j++) {
                    l0 = fmaf(hreg[j], __ldg(wbp + j * D_OUT + o), l0);
                    l1 = fmaf(hreg[j], __ldg(wbp + j * D_OUT + o + 1), l1);
                }
                float2 res;
                res.x = c[mi][ni][2 * hh + 0] + l0;
                res.y = c[mi][ni][2 * hh + 1] + l1;
                *reinterpret_cast<float2*>(out + (size_t)t * D_OUT + o) = res;
            }
        }
    }
}

// ===========================================================================
extern "C" void kernel_launch(void* const* d_in, const int* in_sizes, int n_in,
                              void* d_out, int out_size)
{
    (void)in_sizes; (void)n_in; (void)out_size;
    const float* x       = (const float*)d_in[0];
    const float* base_w  = (const float*)d_in[1];
    const float* base_b  = (const float*)d_in[2];
    const float* wa      = (const float*)d_in[3];
    const float* wb      = (const float*)d_in[4];
    const float* scaling = (const float*)d_in[5];
    const int*   segment = (const int*)d_in[6];
    const int*   lora_id = (const int*)d_in[7];
    float* out = (float*)d_out;

    static cudaStream_t s1 = nullptr;
    static cudaEvent_t e_fork = nullptr, e1 = nullptr;
    static int inited = 0;
    if (!inited) {
        cudaStreamCreateWithFlags(&s1, cudaStreamNonBlocking);
        cudaEventCreateWithFlags(&e_fork, cudaEventDisableTiming);
        cudaEventCreateWithFlags(&e1, cudaEventDisableTiming);
        cudaFuncSetAttribute(fused_gemm_kernel,
                             cudaFuncAttributeMaxDynamicSharedMemorySize, SMEM_TOTAL);
        inited = 1;
    }

    cudaStream_t main_s = 0;
    cudaEventRecord(e_fork, main_s);
    cudaStreamWaitEvent(s1, e_fork, 0);

    // main: fused x prepass (A-fragments + lora partials), then combine
    prep_x_kernel<<<dim3(KSPLIT, T_TOK / 64), 256, 0, main_s>>>(x, wa, segment, lora_id);
    lora_combine_kernel<<<T_TOK * RANK / 4 / 256, 256, 0, main_s>>>(scaling);
    // side: W prepass
    perm_b_kernel<<<dim3(16, 512), 256, 0, s1>>>(base_w);

    cudaEventRecord(e1, s1);
    cudaStreamWaitEvent(main_s, e1, 0);

    dim3 grid(D_OUT / BN, T_TOK / BM);   // (32, 64)
    fused_gemm_kernel<<<grid, 128, SMEM_TOTAL, main_s>>>(base_b, wb, out);
}